// round 9
// baseline (speedup 1.0000x reference)
#include <cuda_runtime.h>
#include <math.h>

#define N_NODES 100000
#define N_EDGES 200000
#define H 128
#define H2 256
#define H3 384
#define NLVL 7
#define NBUCK_E 42        // z*21 + (l-1)*3 + gi ; z=1 -> hf[src] statically zero
#define NBUCK_N 21        // (l-1)*3 + gi
#define MSG_TE 32         // edges per msg tile
#define GRU_TN 8          // nodes per gru tile

// ---------------- device scratch (static: no allocations allowed) ----------
__device__ float g_msg[(size_t)N_NODES * H];   // scatter-add target
__device__ float g_hs_type[6 * H];             // per-gate-type hs row
__device__ float g_hsl1[3 * 6 * H];            // layer1 hs-half table [gi][gtype][j]
__device__ float g_wihT[3 * H * H3];           // transposed GRU input weights [gi][k][row]
__device__ int g_ecount[NBUCK_E];
__device__ int g_eoff[NBUCK_E + 1];
__device__ int g_ecur[NBUCK_E];
__device__ int g_etile[NBUCK_E + 1];
__device__ int g_ncount[NBUCK_N];
__device__ int g_noff[NBUCK_N + 1];
__device__ int g_ncur[NBUCK_N];
__device__ int g_ntile[NBUCK_N + 1];
__device__ int g_elist[N_EDGES];
__device__ int g_nlist[N_NODES];

__device__ __forceinline__ int gate_gi(int g) {
    // GATE_CODES = (3, 2, 5) -> gi 0, 1, 2
    return (g == 3) ? 0 : (g == 2) ? 1 : (g == 5) ? 2 : -1;
}

// edge bucket: z*21 + (l-1)*3 + gi   (z=1: hf[src] statically zero)
__device__ __forceinline__ int edge_bucket(int src, int dst,
                                           const int* gate, const int* lvl) {
    int gi = gate_gi(gate[dst]);
    int l = lvl[dst];
    if (gi < 0 || l < 1 || l > NLVL) return -1;
    int gs = gate_gi(gate[src]);
    int ls = lvl[src];
    int z = !(gs >= 0 && ls >= 1 && ls < l);
    return z * 21 + (l - 1) * 3 + gi;
}

// ---------------- setup kernels -------------------------------------------

// hs_type + bucket-count init (independent, fused to save a launch)
__global__ void k_hs_type(const float* __restrict__ Ws, const float* __restrict__ Wt,
                          const float* __restrict__ hsW, const float* __restrict__ hsb) {
    int g = blockIdx.x;      // 0..5
    int j = threadIdx.x;     // 0..127
    if (g == 0 && j < NBUCK_E) g_ecount[j] = 0;
    if (g == 1 && j < NBUCK_N) g_ncount[j] = 0;
    float acc = hsb[j];
#pragma unroll 4
    for (int k = 0; k < H; k++)
        acc = fmaf(Ws[g * H + k], hsW[k * H + j], acc);
#pragma unroll 4
    for (int k = 0; k < H; k++)
        acc = fmaf(Wt[g * H + k], hsW[(H + k) * H + j], acc);
    g_hs_type[g * H + j] = acc;
}

// layer1 hs-half table: hsl1[gi][g][j] = sum_k hs_type[g][k] * w1[gi][k][j]
__global__ void k_hsl1(const float* __restrict__ w1) {
    int gi = blockIdx.x;     // 0..2
    int g = blockIdx.y;      // 0..5
    int j = threadIdx.x;     // 0..127
    const float* w = w1 + (size_t)gi * H2 * H;
    float acc = 0.f;
#pragma unroll 4
    for (int k = 0; k < H; k++)
        acc = fmaf(g_hs_type[g * H + k], w[k * H + j], acc);
    g_hsl1[(gi * 6 + g) * H + j] = acc;
}

// transpose GRU input weights: wihT[gi][k][r] = wih[gi][r][k]
__global__ void k_transpose(const float* __restrict__ wih) {
    const int total = 3 * H3 * H;
    for (int i = blockIdx.x * blockDim.x + threadIdx.x; i < total; i += gridDim.x * blockDim.x) {
        int gi = i / (H3 * H);
        int rem = i - gi * (H3 * H);
        int r = rem / H;
        int k = rem - r * H;
        g_wihT[gi * H * H3 + k * H3 + r] = wih[i];
    }
}

// write hs to out[0:NH), zero hf region out[NH:2NH), zero msg buffer (float4)
__global__ void k_hs_fill(float4* __restrict__ out4, const int* __restrict__ gate) {
    const int total4 = N_NODES * (H / 4);
    const float4* hs4 = (const float4*)g_hs_type;
    float4* msg4 = (float4*)g_msg;
    const float4 z4 = make_float4(0.f, 0.f, 0.f, 0.f);
    for (int i = blockIdx.x * blockDim.x + threadIdx.x; i < total4; i += gridDim.x * blockDim.x) {
        int node = i >> 5;               // H/4 = 32 float4 per row
        int c = i & 31;
        out4[i] = hs4[gate[node] * 32 + c];
        out4[total4 + i] = z4;
        msg4[i] = z4;
    }
}

// count edges/nodes per bucket
__global__ void k_count(const int* __restrict__ ei, const int* __restrict__ gate,
                        const int* __restrict__ lvl) {
    const int total = N_EDGES + N_NODES;
    for (int i = blockIdx.x * blockDim.x + threadIdx.x; i < total; i += gridDim.x * blockDim.x) {
        if (i < N_EDGES) {
            int b = edge_bucket(ei[i], ei[N_EDGES + i], gate, lvl);
            if (b >= 0) atomicAdd(&g_ecount[b], 1);
        } else {
            int n = i - N_EDGES;
            int gi = gate_gi(gate[n]);
            int l = lvl[n];
            if (gi >= 0 && l >= 1 && l <= NLVL) atomicAdd(&g_ncount[(l - 1) * 3 + gi], 1);
        }
    }
}

__global__ void k_scan() {
    if (threadIdx.x == 0) {
        int s = 0, st = 0;
        for (int b = 0; b < NBUCK_E; b++) {
            g_eoff[b] = s; g_ecur[b] = s; g_etile[b] = st;
            st += (g_ecount[b] + MSG_TE - 1) / MSG_TE;
            s += g_ecount[b];
        }
        g_eoff[NBUCK_E] = s; g_etile[NBUCK_E] = st;
        s = 0; st = 0;
        for (int b = 0; b < NBUCK_N; b++) {
            g_noff[b] = s; g_ncur[b] = s; g_ntile[b] = st;
            st += (g_ncount[b] + GRU_TN - 1) / GRU_TN;
            s += g_ncount[b];
        }
        g_noff[NBUCK_N] = s; g_ntile[NBUCK_N] = st;
    }
}

__global__ void k_fill_lists(const int* __restrict__ ei, const int* __restrict__ gate,
                             const int* __restrict__ lvl) {
    const int total = N_EDGES + N_NODES;
    for (int i = blockIdx.x * blockDim.x + threadIdx.x; i < total; i += gridDim.x * blockDim.x) {
        if (i < N_EDGES) {
            int b = edge_bucket(ei[i], ei[N_EDGES + i], gate, lvl);
            if (b >= 0) {
                int pos = atomicAdd(&g_ecur[b], 1);
                g_elist[pos] = i;
            }
        } else {
            int n = i - N_EDGES;
            int gi = gate_gi(gate[n]);
            int l = lvl[n];
            if (gi >= 0 && l >= 1 && l <= NLVL) {
                int pos = atomicAdd(&g_ncur[(l - 1) * 3 + gi], 1);
                g_nlist[pos] = n;
            }
        }
    }
}

// ---------------- message kernel over a bucket range ----------------------
// Processes edge buckets [bBase, bBase+bCnt). Bucket id encodes z (hf zero?)
// and gi. Block = 128 threads, tile = 32 edges; thread owns cols (c0, c0+64)
// x 16 edges. layer1 = hsl1[gate[src]] (+ hf[src] @ w1[128:256] if z==0) + b1.
__global__ void __launch_bounds__(128) k_msg_range(
        const int* __restrict__ ei, const int* __restrict__ gate,
        const float* __restrict__ outbuf,
        const float* __restrict__ w1a, const float* __restrict__ b1a,
        const float* __restrict__ w2a, const float* __restrict__ b2a,
        const float* __restrict__ w3a, const float* __restrict__ b3a,
        int bBase, int bCnt) {
    __shared__ float4 hfs4[MSG_TE][H / 4];   // 16 KB: hf[src] stage (z==0 only)
    __shared__ float4 h14[MSG_TE][H / 4];    // 16 KB
    __shared__ float4 h24[MSG_TE][H / 4];    // 16 KB
    __shared__ int ssrc[MSG_TE];
    __shared__ int sdst[MSG_TE];
    __shared__ int sgt[MSG_TE];              // gate[src]

    const int t0 = g_etile[bBase];
    const int tN = g_etile[bBase + bCnt];
    const int tid = threadIdx.x;
    const int lane = tid & 31, wrp = tid >> 5;
    const int c0 = tid & 63;                 // cols c0 and c0+64
    const int eh = tid >> 6;                 // edge half: 0 or 1
    const float* hf = outbuf + (size_t)N_NODES * H;

    for (int g = t0 + blockIdx.x; g < tN; g += gridDim.x) {
        int b = bBase;
        while (b < bBase + bCnt - 1 && g >= g_etile[b + 1]) b++;
        const int hfz = b / 21;              // 1 -> hf[src] statically zero
        const int gi = b % 3;
        const int estart = g_eoff[b] + (g - g_etile[b]) * MSG_TE;
        const int ne = min(MSG_TE, g_eoff[b + 1] - estart);
        const float* __restrict__ w1 = w1a + (size_t)gi * H2 * H;
        const float* __restrict__ w2 = w2a + (size_t)gi * H * H;
        const float* __restrict__ w3 = w3a + (size_t)gi * H * H;
        const float* __restrict__ tbl = g_hsl1 + (size_t)gi * 6 * H;

        // ---- stage edge endpoints + src gate type ----
        if (tid < MSG_TE) {
            if (tid < ne) {
                int eid = g_elist[estart + tid];
                int src = ei[eid];
                ssrc[tid] = src;
                sdst[tid] = ei[N_EDGES + eid];
                sgt[tid] = gate[src];
            } else {
                ssrc[tid] = -1;
                sgt[tid] = 0;
            }
        }
        __syncthreads();

        // ---- layer 1 ----
        float acc0[16], acc1[16];
        if (hfz) {
            // pure table lookup, no node-state gather at all
#pragma unroll
            for (int e = 0; e < 16; e++) {
                int gt = sgt[eh * 16 + e];
                acc0[e] = __ldg(&tbl[gt * H + c0]);
                acc1[e] = __ldg(&tbl[gt * H + c0 + 64]);
            }
        } else {
            // gather hf[src] (float4, coalesced per warp)
            for (int p = wrp; p < MSG_TE; p += 4) {
                int src = ssrc[p];
                float4 v = make_float4(0.f, 0.f, 0.f, 0.f);
                if (src >= 0) v = ((const float4*)(hf + (size_t)src * H))[lane];
                hfs4[p][lane] = v;
            }
#pragma unroll
            for (int e = 0; e < 16; e++) {
                int gt = sgt[eh * 16 + e];
                acc0[e] = __ldg(&tbl[gt * H + c0]);
                acc1[e] = __ldg(&tbl[gt * H + c0 + 64]);
            }
            __syncthreads();
            const float* w1b = w1 + (size_t)H * H;   // hf half: rows 128..255
            for (int k4 = 0; k4 < H / 4; k4++) {
                const float* wr = w1b + (k4 * 4) * H;
                float wa0 = wr[c0],         wa1 = wr[H + c0],
                      wa2 = wr[2 * H + c0], wa3 = wr[3 * H + c0];
                float wb0 = wr[c0 + 64],         wb1 = wr[H + c0 + 64],
                      wb2 = wr[2 * H + c0 + 64], wb3 = wr[3 * H + c0 + 64];
#pragma unroll
                for (int e = 0; e < 16; e++) {
                    float4 x = hfs4[eh * 16 + e][k4];
                    acc0[e] = fmaf(x.x, wa0, acc0[e]); acc0[e] = fmaf(x.y, wa1, acc0[e]);
                    acc0[e] = fmaf(x.z, wa2, acc0[e]); acc0[e] = fmaf(x.w, wa3, acc0[e]);
                    acc1[e] = fmaf(x.x, wb0, acc1[e]); acc1[e] = fmaf(x.y, wb1, acc1[e]);
                    acc1[e] = fmaf(x.z, wb2, acc1[e]); acc1[e] = fmaf(x.w, wb3, acc1[e]);
                }
            }
        }
        {
            float bb0 = b1a[gi * H + c0], bb1 = b1a[gi * H + c0 + 64];
            float* h1f = (float*)h14;
#pragma unroll
            for (int e = 0; e < 16; e++) {
                int ge = eh * 16 + e;
                h1f[ge * H + c0]      = fmaxf(acc0[e] + bb0, 0.f);
                h1f[ge * H + c0 + 64] = fmaxf(acc1[e] + bb1, 0.f);
            }
        }
        __syncthreads();

        // ---- layer 2: [32,128] x [128,128] ----
#pragma unroll
        for (int e = 0; e < 16; e++) { acc0[e] = 0.f; acc1[e] = 0.f; }
        for (int k4 = 0; k4 < H / 4; k4++) {
            const float* wr = w2 + (k4 * 4) * H;
            float wa0 = wr[c0],         wa1 = wr[H + c0],
                  wa2 = wr[2 * H + c0], wa3 = wr[3 * H + c0];
            float wb0 = wr[c0 + 64],         wb1 = wr[H + c0 + 64],
                  wb2 = wr[2 * H + c0 + 64], wb3 = wr[3 * H + c0 + 64];
#pragma unroll
            for (int e = 0; e < 16; e++) {
                float4 x = h14[eh * 16 + e][k4];
                acc0[e] = fmaf(x.x, wa0, acc0[e]); acc0[e] = fmaf(x.y, wa1, acc0[e]);
                acc0[e] = fmaf(x.z, wa2, acc0[e]); acc0[e] = fmaf(x.w, wa3, acc0[e]);
                acc1[e] = fmaf(x.x, wb0, acc1[e]); acc1[e] = fmaf(x.y, wb1, acc1[e]);
                acc1[e] = fmaf(x.z, wb2, acc1[e]); acc1[e] = fmaf(x.w, wb3, acc1[e]);
            }
        }
        {
            float bb0 = b2a[gi * H + c0], bb1 = b2a[gi * H + c0 + 64];
            float* h2f = (float*)h24;
#pragma unroll
            for (int e = 0; e < 16; e++) {
                int ge = eh * 16 + e;
                h2f[ge * H + c0]      = fmaxf(acc0[e] + bb0, 0.f);
                h2f[ge * H + c0 + 64] = fmaxf(acc1[e] + bb1, 0.f);
            }
        }
        __syncthreads();

        // ---- layer 3: [32,128] x [128,128] -> scatter-add ----
#pragma unroll
        for (int e = 0; e < 16; e++) { acc0[e] = 0.f; acc1[e] = 0.f; }
        for (int k4 = 0; k4 < H / 4; k4++) {
            const float* wr = w3 + (k4 * 4) * H;
            float wa0 = wr[c0],         wa1 = wr[H + c0],
                  wa2 = wr[2 * H + c0], wa3 = wr[3 * H + c0];
            float wb0 = wr[c0 + 64],         wb1 = wr[H + c0 + 64],
                  wb2 = wr[2 * H + c0 + 64], wb3 = wr[3 * H + c0 + 64];
#pragma unroll
            for (int e = 0; e < 16; e++) {
                float4 x = h24[eh * 16 + e][k4];
                acc0[e] = fmaf(x.x, wa0, acc0[e]); acc0[e] = fmaf(x.y, wa1, acc0[e]);
                acc0[e] = fmaf(x.z, wa2, acc0[e]); acc0[e] = fmaf(x.w, wa3, acc0[e]);
                acc1[e] = fmaf(x.x, wb0, acc1[e]); acc1[e] = fmaf(x.y, wb1, acc1[e]);
                acc1[e] = fmaf(x.z, wb2, acc1[e]); acc1[e] = fmaf(x.w, wb3, acc1[e]);
            }
        }
        {
            float bb0 = b3a[gi * H + c0], bb1 = b3a[gi * H + c0 + 64];
            for (int e = 0; e < 16; e++) {
                int ge = eh * 16 + e;
                if (ge < ne) {
                    int d = sdst[ge];
                    atomicAdd(&g_msg[(size_t)d * H + c0],      acc0[e] + bb0);
                    atomicAdd(&g_msg[(size_t)d * H + c0 + 64], acc1[e] + bb1);
                }
            }
        }
        __syncthreads();
    }
}

// ---------------- fused per-level GRU kernel ------------------------------
// h_old is provably zero (each node updated exactly once): whh GEMM -> bhh bias.
__global__ void __launch_bounds__(128) k_gru_lvl(
        const float* __restrict__ bih_a, const float* __restrict__ bhh_a,
        float* __restrict__ outbuf, int lvl) {
    __shared__ float4 ms4[GRU_TN][H / 4];
    __shared__ int snode[GRU_TN];

    const int b0 = (lvl - 1) * 3;
    const int t0 = g_ntile[b0];
    const int t3 = g_ntile[b0 + 3];
    const int tid = threadIdx.x;
    const int lane = tid & 31, wrp = tid >> 5;
    const int j = tid;
    float* hf = outbuf + (size_t)N_NODES * H;

    for (int g = t0 + blockIdx.x; g < t3; g += gridDim.x) {
        int b = b0;
        while (b < b0 + 2 && g >= g_ntile[b + 1]) b++;
        const int gi = b - b0;
        const int nstart = g_noff[b] + (g - g_ntile[b]) * GRU_TN;
        const int nn = min(GRU_TN, g_noff[b + 1] - nstart);
        const float* __restrict__ wihT = g_wihT + (size_t)gi * H * H3;

        if (tid < GRU_TN)
            snode[tid] = (tid < nn) ? g_nlist[nstart + tid] : -1;
        __syncthreads();

        if (wrp < GRU_TN / 2) {
            for (int p = wrp; p < GRU_TN; p += 4) {
                int node = snode[p];
                float4 v = make_float4(0.f, 0.f, 0.f, 0.f);
                if (node >= 0) v = ((const float4*)(g_msg + (size_t)node * H))[lane];
                ms4[p][lane] = v;
            }
        }
        __syncthreads();

        float ar[GRU_TN], az[GRU_TN], an[GRU_TN];
#pragma unroll
        for (int e = 0; e < GRU_TN; e++) { ar[e] = 0.f; az[e] = 0.f; an[e] = 0.f; }

        for (int k4 = 0; k4 < H / 4; k4++) {
            const float* wr = wihT + (size_t)(k4 * 4) * H3;
            float r0 = wr[j],            r1 = wr[H3 + j],
                  r2 = wr[2 * H3 + j],   r3 = wr[3 * H3 + j];
            float z0 = wr[H + j],           z1 = wr[H3 + H + j],
                  z2 = wr[2 * H3 + H + j],  z3 = wr[3 * H3 + H + j];
            float n0 = wr[2 * H + j],          n1 = wr[H3 + 2 * H + j],
                  n2 = wr[2 * H3 + 2 * H + j], n3 = wr[3 * H3 + 2 * H + j];
#pragma unroll
            for (int e = 0; e < GRU_TN; e++) {
                float4 m = ms4[e][k4];
                ar[e] = fmaf(m.x, r0, ar[e]); ar[e] = fmaf(m.y, r1, ar[e]);
                ar[e] = fmaf(m.z, r2, ar[e]); ar[e] = fmaf(m.w, r3, ar[e]);
                az[e] = fmaf(m.x, z0, az[e]); az[e] = fmaf(m.y, z1, az[e]);
                az[e] = fmaf(m.z, z2, az[e]); az[e] = fmaf(m.w, z3, az[e]);
                an[e] = fmaf(m.x, n0, an[e]); an[e] = fmaf(m.y, n1, an[e]);
                an[e] = fmaf(m.z, n2, an[e]); an[e] = fmaf(m.w, n3, an[e]);
            }
        }

        const float bir = bih_a[gi * H3 + j]            + bhh_a[gi * H3 + j];
        const float biz = bih_a[gi * H3 + H + j]        + bhh_a[gi * H3 + H + j];
        const float bin_ = bih_a[gi * H3 + 2 * H + j];
        const float bhn  = bhh_a[gi * H3 + 2 * H + j];
        for (int e = 0; e < GRU_TN; e++) {
            int node = snode[e];
            if (node >= 0) {
                float r = 1.0f / (1.0f + expf(-(ar[e] + bir)));
                float z = 1.0f / (1.0f + expf(-(az[e] + biz)));
                float nst = tanhf(an[e] + bin_ + r * bhn);
                hf[(size_t)node * H + j] = (1.0f - z) * nst;
            }
        }
        __syncthreads();
    }
}

// ---------------- launch ---------------------------------------------------

extern "C" void kernel_launch(void* const* d_in, const int* in_sizes, int n_in,
                              void* d_out, int out_size) {
    const int* gate    = (const int*)d_in[0];
    const int* flevel  = (const int*)d_in[1];
    const int* ei      = (const int*)d_in[2];
    const float* Ws    = (const float*)d_in[3];
    const float* Wt    = (const float*)d_in[4];
    const float* hs_W  = (const float*)d_in[5];
    const float* hs_b  = (const float*)d_in[6];
    const float* w1    = (const float*)d_in[7];
    const float* b1    = (const float*)d_in[8];
    const float* w2    = (const float*)d_in[9];
    const float* b2    = (const float*)d_in[10];
    const float* w3    = (const float*)d_in[11];
    const float* b3    = (const float*)d_in[12];
    const float* wih   = (const float*)d_in[13];
    const float* bih   = (const float*)d_in[15];
    const float* bhh   = (const float*)d_in[16];
    float* out = (float*)d_out;

    k_hs_type<<<6, H>>>(Ws, Wt, hs_W, hs_b);
    k_hsl1<<<dim3(3, 6), H>>>(w1);
    k_transpose<<<256, 256>>>(wih);
    k_hs_fill<<<2048, 256>>>((float4*)out, gate);
    k_count<<<1024, 256>>>(ei, gate, flevel);
    k_scan<<<1, 32>>>();
    k_fill_lists<<<1024, 256>>>(ei, gate, flevel);

    // All z=1 (statically-zero-hf) message edges across ALL levels: one
    // full-occupancy launch — they depend only on the gate-type table.
    k_msg_range<<<1184, 128>>>(ei, gate, out, w1, b1, w2, b2, w3, b3, 21, 21);

    for (int lvl = 1; lvl <= 7; lvl++) {
        // z=0 message edges of this level (read hf of earlier levels).
        // Level 1 has none: hf of any src is still zero.
        if (lvl >= 2)
            k_msg_range<<<1184, 128>>>(ei, gate, out, w1, b1, w2, b2, w3, b3,
                                       (lvl - 1) * 3, 3);
        k_gru_lvl<<<1184, 128>>>(bih, bhh, out, lvl);
    }
}